// round 11
// baseline (speedup 1.0000x reference)
#include <cuda_runtime.h>
#include <cuda_bf16.h>
#include <math.h>

// Problem dims
#define Hn 512
#define Dn 128
#define Nn 64
#define Tn 512

// K3 layout: 256 CTAs = 16 n-groups x 16 j-slices, 2 CTAs co-resident/SM
#define K3_G  16
#define K3_J  16
#define K3_NP 4          // sequences per group
#define K3_JC 32         // hidden-state columns per CTA (1 per lane)
#define AP    516        // padded a_s row stride

// ---------------- device scratch (static globals: no allocation) -------------
__device__ float g_E[(size_t)Tn * Nn * Hn];   // emit, then exp(emit - m); [t][n][h]
__device__ float g_M[Tn * Nn];                // rowmax m[t][n]
__device__ float g_Wt[Dn * Hn];               // W^T: [d][h]
__device__ float g_bias[Hn];
__device__ float g_alpha[2][(size_t)Nn * Hn]; // double-buffered scaled alpha
__device__ unsigned g_cnt2[K3_G * 32];        // per-group barrier counters (padded)
__device__ volatile unsigned g_gen2[K3_G * 32];

// ---------------- packed f32x2 helpers ---------------------------------------
__device__ __forceinline__ unsigned long long ffma2(unsigned long long a,
                                                    unsigned long long b,
                                                    unsigned long long c) {
    unsigned long long d;
    asm("fma.rn.f32x2 %0, %1, %2, %3;" : "=l"(d) : "l"(a), "l"(b), "l"(c));
    return d;
}
__device__ __forceinline__ float2 up2(unsigned long long v) {
    float2 r;
    asm("mov.b64 {%0, %1}, %2;" : "=f"(r.x), "=f"(r.y) : "l"(v));
    return r;
}
__device__ __forceinline__ unsigned long long pack2(float lo, float hi) {
    unsigned long long v;
    asm("mov.b64 %0, {%1, %2};" : "=l"(v) : "f"(lo), "f"(hi));
    return v;
}

// ---------------- K0: W^T and bias ------------------------------------------
__global__ void hmm_k0(const float* __restrict__ py) {
    int h = blockIdx.x * 8 + (threadIdx.x >> 5);
    int lane = threadIdx.x & 31;
    float s = 0.f;
#pragma unroll
    for (int c = 0; c < 4; c++) {
        int d = lane + c * 32;
        float p = __ldg(py + (size_t)h * Dn + d);
        float l1 = log1pf(-p);
        g_Wt[(size_t)d * Hn + h] = logf(p) - l1;
        s += l1;
    }
#pragma unroll
    for (int o = 16; o; o >>= 1) s += __shfl_xor_sync(0xffffffffu, s, o);
    if (lane == 0) g_bias[h] = s;
}

// ---------------- K1: emission GEMM  emit[t][n][h] = seq[n,t,:]*W^T + b ------
#define K1_SMEM ((64 * 132 + 128 * 128) * 4)
__global__ void __launch_bounds__(256) hmm_k1(const float* __restrict__ seq) {
    extern __shared__ float sm1[];
    float* seq_s = sm1;              // [64][132]
    float* W_s   = sm1 + 64 * 132;   // [128 k][128 h]

    int tid = threadIdx.x;
    int tb = blockIdx.y;
    int h0 = blockIdx.x * 128;

    for (int idx = tid; idx < 64 * 32; idx += 256) {
        int n = idx >> 5, d4 = idx & 31;
        float4 v = __ldg((const float4*)(seq + ((size_t)n * Tn + tb) * Dn + d4 * 4));
        *(float4*)&seq_s[n * 132 + d4 * 4] = v;
    }
    for (int idx = tid; idx < 128 * 32; idx += 256) {
        int k = idx >> 5, h4 = idx & 31;
        float4 v = __ldg((const float4*)(g_Wt + (size_t)k * Hn + h0 + h4 * 4));
        *(float4*)&W_s[k * 128 + h4 * 4] = v;
    }
    __syncthreads();

    int tx = tid & 15;
    int ty = tid >> 4;
    float acc[4][8];
#pragma unroll
    for (int u = 0; u < 4; u++)
#pragma unroll
        for (int v = 0; v < 8; v++) acc[u][v] = 0.f;

#pragma unroll 4
    for (int k = 0; k < 128; k++) {
        float aa[4];
#pragma unroll
        for (int u = 0; u < 4; u++) aa[u] = seq_s[(ty * 4 + u) * 132 + k];
        float4 b0 = *(const float4*)&W_s[k * 128 + tx * 8];
        float4 b1 = *(const float4*)&W_s[k * 128 + tx * 8 + 4];
        float bb[8] = {b0.x, b0.y, b0.z, b0.w, b1.x, b1.y, b1.z, b1.w};
#pragma unroll
        for (int u = 0; u < 4; u++)
#pragma unroll
            for (int v = 0; v < 8; v++) acc[u][v] = fmaf(aa[u], bb[v], acc[u][v]);
    }

    float4 bi0 = *(const float4*)&g_bias[h0 + tx * 8];
    float4 bi1 = *(const float4*)&g_bias[h0 + tx * 8 + 4];
    float bb[8] = {bi0.x, bi0.y, bi0.z, bi0.w, bi1.x, bi1.y, bi1.z, bi1.w};
#pragma unroll
    for (int u = 0; u < 4; u++) {
        size_t r = (size_t)tb * 64 + ty * 4 + u;
        float4 o0 = make_float4(acc[u][0] + bb[0], acc[u][1] + bb[1],
                                acc[u][2] + bb[2], acc[u][3] + bb[3]);
        float4 o1 = make_float4(acc[u][4] + bb[4], acc[u][5] + bb[5],
                                acc[u][6] + bb[6], acc[u][7] + bb[7]);
        *(float4*)&g_E[r * Hn + h0 + tx * 8]     = o0;
        *(float4*)&g_E[r * Hn + h0 + tx * 8 + 4] = o1;
    }
}

// ---------------- K2: rowmax + exp(emit - m), in place; write m --------------
__global__ void __launch_bounds__(256) hmm_k2() {
    int r = blockIdx.x * 8 + (threadIdx.x >> 5);
    int lane = threadIdx.x & 31;
    float* row = g_E + (size_t)r * Hn;
    float4 v[4];
    float m = -3.0e38f;
#pragma unroll
    for (int c = 0; c < 4; c++) {
        v[c] = *(const float4*)(row + c * 128 + lane * 4);
        m = fmaxf(m, fmaxf(fmaxf(v[c].x, v[c].y), fmaxf(v[c].z, v[c].w)));
    }
#pragma unroll
    for (int o = 16; o; o >>= 1) m = fmaxf(m, __shfl_xor_sync(0xffffffffu, m, o));
#pragma unroll
    for (int c = 0; c < 4; c++) {
        float4 e = make_float4(__expf(v[c].x - m), __expf(v[c].y - m),
                               __expf(v[c].z - m), __expf(v[c].w - m));
        *(float4*)(row + c * 128 + lane * 4) = e;
    }
    if (lane == 0) g_M[r] = m;
}

// ---------------- per-group grid barrier (16 CTAs, self-resetting) -----------
__device__ __forceinline__ void gridbar(unsigned gb) {
    __threadfence();
    __syncthreads();
    if (threadIdx.x == 0) {
        unsigned gen = g_gen2[gb];
        unsigned a = atomicAdd(&g_cnt2[gb], 1u);
        if (a == K3_J - 1u) {
            atomicExch(&g_cnt2[gb], 0u);
            __threadfence();
            g_gen2[gb] = gen + 1u;
        } else {
            while (g_gen2[gb] == gen) { }
            __threadfence();
        }
    }
    __syncthreads();
}

// ---------------- K3: P-in-registers scaled-forward, 2 CTAs/SM ---------------
// Thread (w, lane): i-chunk = w*64 (P rows), j-column = j0 + lane.
// Warp w<4 owns sequence n0+w (staging, combine, output).
__global__ void __launch_bounds__(256, 2) hmm_k3(const float* __restrict__ px,
                                                 const int* __restrict__ lengths,
                                                 float* __restrict__ out) {
    __shared__ float a_s[K3_NP * AP];           // staged alpha rows [4][516]
    __shared__ float rsum[K3_NP * 8 * 32];      // partials [n][chunk][j]
    __shared__ float R_s[K3_NP];                // 1/S per sequence
    __shared__ int   len_s[K3_NP];

    const int tid  = threadIdx.x;
    const int w    = tid >> 5;                  // warp = i-chunk
    const int lane = tid & 31;                  // j-column within slice
    const int cta  = blockIdx.x;
    const int jsl  = cta & (K3_J - 1);
    const int g    = cta >> 4;
    const int n0   = g * K3_NP;
    const int j0   = jsl * K3_JC;
    const int jg   = j0 + lane;
    const unsigned gb = (unsigned)g * 32u;
    const bool owner = (w < K3_NP);

    // P slice -> registers: Pp[k] packs P[w*64+2k][jg], P[w*64+2k+1][jg]
    unsigned long long Pp[32];
#pragma unroll
    for (int k = 0; k < 32; k++) {
        float p0 = __ldg(px + (size_t)(w * 64 + 2 * k)     * Hn + jg);
        float p1 = __ldg(px + (size_t)(w * 64 + 2 * k + 1) * Hn + jg);
        Pp[k] = pack2(p0, p1);
    }
    if (tid < K3_NP) len_s[tid] = __ldg(lengths + n0 + tid);
    __syncthreads();
    const int lenw = len_s[w & (K3_NP - 1)];

    // ---- t = 0 init: a0 = probs_x[0][j] * E[0][n][j];  Creg = m0 ----
    float accv = 0.f;
    if (owner) {
        accv = __ldg(px + jg) * __ldcg(g_E + (size_t)(n0 + w) * Hn + jg);
        __stcg(&g_alpha[0][(size_t)(n0 + w) * Hn + jg], accv);
    }
    float Creg = 0.f;
    if (jsl == 0 && owner && lane == 0) Creg = __ldg(g_M + n0 + w);
    gridbar(gb);

    for (int t = 1; t < Tn; t++) {
        const int rb = (t - 1) & 1;
        const int wb = t & 1;

        float e = 0.f, mreg = 0.f;
        if (owner) {
            e = __ldcg(g_E + ((size_t)t * Nn + n0 + w) * Hn + jg);
            if (jsl == 0 && lane == 0)
                mreg = __ldg(g_M + (size_t)t * Nn + n0 + w);
        }

        // stage alpha rows (warps 0..3 <-> sequences n0..n0+3) + row sum S
        if (owner) {
            const float* ar = g_alpha[rb] + (size_t)(n0 + w) * Hn;
            float ssum = 0.f;
#pragma unroll
            for (int c = 0; c < 4; c++) {
                int i = c * 128 + lane * 4;
                float4 v = __ldcg((const float4*)(ar + i));
                ssum += (v.x + v.y) + (v.z + v.w);
                *(float4*)&a_s[w * AP + i] = v;
            }
#pragma unroll
            for (int o = 16; o; o >>= 1) ssum += __shfl_xor_sync(0xffffffffu, ssum, o);
            if (lane == 0) {
                R_s[w] = 1.0f / ssum;
                if (jsl == 0 && t < lenw) Creg += logf(ssum) + mreg;
            }
        }
        __syncthreads();

        // partial dots: for each sequence n, over this thread's 64-i chunk
#pragma unroll
        for (int n = 0; n < K3_NP; n++) {
            const ulonglong2* an = (const ulonglong2*)(a_s + n * AP + (w << 6));
            unsigned long long q0 = 0ull, q1 = 0ull;
#pragma unroll
            for (int k = 0; k < 16; k++) {
                ulonglong2 av = an[k];                 // broadcast LDS.128
                q0 = ffma2(av.x, Pp[2 * k],     q0);
                q1 = ffma2(av.y, Pp[2 * k + 1], q1);
            }
            float2 f0 = up2(q0), f1 = up2(q1);
            rsum[(n * 8 + w) * 32 + lane] = (f0.x + f0.y) + (f1.x + f1.y);
        }
        __syncthreads();

        // combine 8 i-chunks: warp w<4 finishes sequence n0+w, column jg
        if (owner) {
            float tot = 0.f;
#pragma unroll
            for (int c = 0; c < 8; c++) tot += rsum[(w * 8 + c) * 32 + lane];
            float newv = tot * R_s[w] * e;
            if (t < lenw) accv = newv;                 // frozen copy-through
            __stcg(&g_alpha[wb][(size_t)(n0 + w) * Hn + jg], accv);
        }
        gridbar(gb);
    }

    // ---- output: j-slice-0 CTAs, warp w<4 <-> sequence n0+w ----
    if (jsl == 0 && owner) {
        const float* ar = g_alpha[(Tn - 1) & 1] + (size_t)(n0 + w) * Hn;
        float s = 0.f;
#pragma unroll
        for (int c = 0; c < 4; c++) {
            int i = c * 128 + lane * 4;
            float4 v = __ldcg((const float4*)(ar + i));
            s += (v.x + v.y) + (v.z + v.w);
        }
#pragma unroll
        for (int o = 16; o; o >>= 1) s += __shfl_xor_sync(0xffffffffu, s, o);
        if (lane == 0) out[n0 + w] = Creg + logf(s);
    }
}

// ---------------- launch ------------------------------------------------------
extern "C" void kernel_launch(void* const* d_in, const int* in_sizes, int n_in,
                              void* d_out, int out_size) {
    const float* seq = nullptr;
    const int*   len = nullptr;
    const float* px  = nullptr;
    const float* py  = nullptr;
    for (int i = 0; i < n_in; i++) {
        switch (in_sizes[i]) {
            case Nn * Tn * Dn: seq = (const float*)d_in[i]; break;
            case Nn:           len = (const int*)d_in[i];   break;
            case Hn * Hn:      px  = (const float*)d_in[i]; break;
            case Hn * Dn:      py  = (const float*)d_in[i]; break;
        }
    }

    cudaFuncSetAttribute(hmm_k1, cudaFuncAttributeMaxDynamicSharedMemorySize, K1_SMEM);

    hmm_k0<<<64, 256>>>(py);
    hmm_k1<<<dim3(4, 512), 256, K1_SMEM>>>(seq);
    hmm_k2<<<4096, 256>>>();
    hmm_k3<<<K3_G * K3_J, 256>>>(px, len, (float*)d_out);
}

// round 12
// speedup vs baseline: 1.4160x; 1.4160x over previous
#include <cuda_runtime.h>
#include <cuda_bf16.h>
#include <math.h>

// Problem dims
#define Hn 512
#define Dn 128
#define Nn 64
#define Tn 512

// K3 topology: 16 clusters x 8 CTAs. Cluster = 1 group of 4 sequences.
// CTA: 256 threads, owns 64 j-columns, P slice in registers (64 ull/thread).
#define K3_CL 8
#define K3_NP 4
#define K3_JC 64
#define AP    516                 // buf row stride (floats), 16B-aligned
#define RX_BYTES 8448u            // per-phase incoming: 8 ranks * (256*4 + 8*4)

// ---------------- device scratch (static globals: no allocation) -------------
__device__ float g_E[(size_t)Tn * Nn * Hn];   // emit, then exp(emit - m); [t][n][h]
__device__ float g_M[Tn * Nn];                // rowmax m[t][n]
__device__ float g_Wt[Dn * Hn];               // W^T: [d][h]
__device__ float g_bias[Hn];

// ---------------- helpers -----------------------------------------------------
__device__ __forceinline__ unsigned long long ffma2(unsigned long long a,
                                                    unsigned long long b,
                                                    unsigned long long c) {
    unsigned long long d;
    asm("fma.rn.f32x2 %0, %1, %2, %3;" : "=l"(d) : "l"(a), "l"(b), "l"(c));
    return d;
}
__device__ __forceinline__ float2 up2(unsigned long long v) {
    float2 r;
    asm("mov.b64 {%0, %1}, %2;" : "=f"(r.x), "=f"(r.y) : "l"(v));
    return r;
}
__device__ __forceinline__ unsigned long long pack2(float lo, float hi) {
    unsigned long long v;
    asm("mov.b64 %0, {%1, %2};" : "=l"(v) : "f"(lo), "f"(hi));
    return v;
}
__device__ __forceinline__ unsigned smem_u32(const void* p) {
    return (unsigned)__cvta_generic_to_shared(p);
}
__device__ __forceinline__ unsigned mapa_rank(unsigned saddr, unsigned rank) {
    unsigned r;
    asm("mapa.shared::cluster.u32 %0, %1, %2;" : "=r"(r) : "r"(saddr), "r"(rank));
    return r;
}
// Remote store with transaction-count completion on the destination mbarrier.
__device__ __forceinline__ void st_async_f32(unsigned laddr, unsigned lmbar,
                                             unsigned rank, float v) {
    unsigned ra = mapa_rank(laddr, rank);
    unsigned rb = mapa_rank(lmbar, rank);
    asm volatile(
        "st.async.shared::cluster.mbarrier::complete_tx::bytes.b32 [%0], %1, [%2];"
        :: "r"(ra), "r"(__float_as_uint(v)), "r"(rb) : "memory");
}
__device__ __forceinline__ void mbar_init(unsigned mbar, unsigned count) {
    asm volatile("mbarrier.init.shared.b64 [%0], %1;" :: "r"(mbar), "r"(count) : "memory");
}
__device__ __forceinline__ void mbar_expect(unsigned mbar, unsigned bytes) {
    asm volatile("mbarrier.arrive.expect_tx.shared.b64 _, [%0], %1;"
                 :: "r"(mbar), "r"(bytes) : "memory");
}
__device__ __forceinline__ void mbar_wait(unsigned mbar, unsigned parity) {
    asm volatile(
        "{\n\t.reg .pred P1;\n\t"
        "WL_%=:\n\t"
        "mbarrier.try_wait.parity.acquire.cluster.shared::cta.b64 P1, [%0], %1, 0x989680;\n\t"
        "@P1 bra.uni WD_%=;\n\t"
        "bra.uni WL_%=;\n\t"
        "WD_%=:\n\t}"
        :: "r"(mbar), "r"(parity) : "memory");
}
__device__ __forceinline__ void cluster_sync_hw() {
    asm volatile("barrier.cluster.arrive.aligned;" ::: "memory");
    asm volatile("barrier.cluster.wait.aligned;" ::: "memory");
}

// ---------------- K0: W^T and bias ------------------------------------------
__global__ void hmm_k0(const float* __restrict__ py) {
    int h = blockIdx.x * 8 + (threadIdx.x >> 5);
    int lane = threadIdx.x & 31;
    float s = 0.f;
#pragma unroll
    for (int c = 0; c < 4; c++) {
        int d = lane + c * 32;
        float p = __ldg(py + (size_t)h * Dn + d);
        float l1 = log1pf(-p);
        g_Wt[(size_t)d * Hn + h] = logf(p) - l1;
        s += l1;
    }
#pragma unroll
    for (int o = 16; o; o >>= 1) s += __shfl_xor_sync(0xffffffffu, s, o);
    if (lane == 0) g_bias[h] = s;
}

// ---------------- K1: emission GEMM  emit[t][n][h] = seq[n,t,:]*W^T + b ------
#define K1_SMEM ((64 * 132 + 128 * 128) * 4)
__global__ void __launch_bounds__(256) hmm_k1(const float* __restrict__ seq) {
    extern __shared__ float sm1[];
    float* seq_s = sm1;              // [64][132]
    float* W_s   = sm1 + 64 * 132;   // [128 k][128 h]

    int tid = threadIdx.x;
    int tb = blockIdx.y;
    int h0 = blockIdx.x * 128;

    for (int idx = tid; idx < 64 * 32; idx += 256) {
        int n = idx >> 5, d4 = idx & 31;
        float4 v = __ldg((const float4*)(seq + ((size_t)n * Tn + tb) * Dn + d4 * 4));
        *(float4*)&seq_s[n * 132 + d4 * 4] = v;
    }
    for (int idx = tid; idx < 128 * 32; idx += 256) {
        int k = idx >> 5, h4 = idx & 31;
        float4 v = __ldg((const float4*)(g_Wt + (size_t)k * Hn + h0 + h4 * 4));
        *(float4*)&W_s[k * 128 + h4 * 4] = v;
    }
    __syncthreads();

    int tx = tid & 15;
    int ty = tid >> 4;
    float acc[4][8];
#pragma unroll
    for (int u = 0; u < 4; u++)
#pragma unroll
        for (int v = 0; v < 8; v++) acc[u][v] = 0.f;

#pragma unroll 4
    for (int k = 0; k < 128; k++) {
        float aa[4];
#pragma unroll
        for (int u = 0; u < 4; u++) aa[u] = seq_s[(ty * 4 + u) * 132 + k];
        float4 b0 = *(const float4*)&W_s[k * 128 + tx * 8];
        float4 b1 = *(const float4*)&W_s[k * 128 + tx * 8 + 4];
        float bb[8] = {b0.x, b0.y, b0.z, b0.w, b1.x, b1.y, b1.z, b1.w};
#pragma unroll
        for (int u = 0; u < 4; u++)
#pragma unroll
            for (int v = 0; v < 8; v++) acc[u][v] = fmaf(aa[u], bb[v], acc[u][v]);
    }

    float4 bi0 = *(const float4*)&g_bias[h0 + tx * 8];
    float4 bi1 = *(const float4*)&g_bias[h0 + tx * 8 + 4];
    float bb[8] = {bi0.x, bi0.y, bi0.z, bi0.w, bi1.x, bi1.y, bi1.z, bi1.w};
#pragma unroll
    for (int u = 0; u < 4; u++) {
        size_t r = (size_t)tb * 64 + ty * 4 + u;
        float4 o0 = make_float4(acc[u][0] + bb[0], acc[u][1] + bb[1],
                                acc[u][2] + bb[2], acc[u][3] + bb[3]);
        float4 o1 = make_float4(acc[u][4] + bb[4], acc[u][5] + bb[5],
                                acc[u][6] + bb[6], acc[u][7] + bb[7]);
        *(float4*)&g_E[r * Hn + h0 + tx * 8]     = o0;
        *(float4*)&g_E[r * Hn + h0 + tx * 8 + 4] = o1;
    }
}

// ---------------- K2: rowmax + exp(emit - m), in place; write m --------------
__global__ void __launch_bounds__(256) hmm_k2() {
    int r = blockIdx.x * 8 + (threadIdx.x >> 5);
    int lane = threadIdx.x & 31;
    float* row = g_E + (size_t)r * Hn;
    float4 v[4];
    float m = -3.0e38f;
#pragma unroll
    for (int c = 0; c < 4; c++) {
        v[c] = *(const float4*)(row + c * 128 + lane * 4);
        m = fmaxf(m, fmaxf(fmaxf(v[c].x, v[c].y), fmaxf(v[c].z, v[c].w)));
    }
#pragma unroll
    for (int o = 16; o; o >>= 1) m = fmaxf(m, __shfl_xor_sync(0xffffffffu, m, o));
#pragma unroll
    for (int c = 0; c < 4; c++) {
        float4 e = make_float4(__expf(v[c].x - m), __expf(v[c].y - m),
                               __expf(v[c].z - m), __expf(v[c].w - m));
        *(float4*)(row + c * 128 + lane * 4) = e;
    }
    if (lane == 0) g_M[r] = m;
}

// ---------------- K3: cluster st.async scaled-forward recursion --------------
// Thread roles:
//   dot:     (w, lane): i-chunk = [64w, 64w+64), j-cols {lane, lane+32} (local)
//   combine: tid <-> (s = tid>>6, jloc = tid&63), jglob = 64*rank + jloc
__global__ void __launch_bounds__(256, 1) __cluster_dims__(K3_CL, 1, 1)
hmm_k3(const float* __restrict__ px, const int* __restrict__ lengths,
       float* __restrict__ out) {
    __shared__ float buf[2][K3_NP][AP];     // incoming alpha, double-buffered
    __shared__ float rsum[256 * 9];         // partials [(s*64+jloc)*9 + w]
    __shared__ float ps[2][K3_CL][8];       // per-rank per-warp partial sums
    __shared__ float R_s[K3_NP];            // 1/S per sequence
    __shared__ int   len_s[K3_NP];
    __shared__ unsigned long long mbar[2];

    const int tid  = threadIdx.x;
    const int w    = tid >> 5;
    const int lane = tid & 31;
    unsigned rank;
    asm("mov.u32 %0, %%cluster_ctarank;" : "=r"(rank));
    const int grp = blockIdx.x >> 3;             // cluster id 0..15
    const int n0  = grp * K3_NP;

    // combine-owner identity
    const int s_own   = tid >> 6;                // 0..3
    const int jloc    = tid & 63;
    const int jglob   = (int)rank * K3_JC + jloc;
    // dot identity j-columns
    const int jg0 = (int)rank * K3_JC + lane;
    const int jg1 = jg0 + 32;

    const unsigned mb0 = smem_u32(&mbar[0]);
    const unsigned mb1 = smem_u32(&mbar[1]);

    // P slice -> registers: Pp[j][k] packs P[64w+2k][jg_j], P[64w+2k+1][jg_j]
    unsigned long long Pp[2][32];
#pragma unroll
    for (int k = 0; k < 32; k++) {
        const float* pr0 = px + (size_t)(w * 64 + 2 * k) * Hn;
        const float* pr1 = px + (size_t)(w * 64 + 2 * k + 1) * Hn;
        Pp[0][k] = pack2(__ldg(pr0 + jg0), __ldg(pr1 + jg0));
        Pp[1][k] = pack2(__ldg(pr0 + jg1), __ldg(pr1 + jg1));
    }
    if (tid == 0) {
        mbar_init(mb0, 1);
        mbar_init(mb1, 1);
    }
    if (tid < K3_NP) len_s[tid] = __ldg(lengths + n0 + tid);
    __syncthreads();
    if (tid == 0) {                               // arm both phases' tx counts
        mbar_expect(mb0, RX_BYTES);
        mbar_expect(mb1, RX_BYTES);
    }
    const int mylen = len_s[s_own];
    cluster_sync_hw();                            // one-time: inits visible

    // push addresses (local-equivalent offsets, same in every rank)
    const unsigned a_off0 = smem_u32(&buf[0][s_own][jglob]);
    const unsigned a_off1 = smem_u32(&buf[1][s_own][jglob]);
    const unsigned p_off0 = smem_u32(&ps[0][rank][w]);
    const unsigned p_off1 = smem_u32(&ps[1][rank][w]);

    const bool scomp = (w < K3_NP && lane == 0);  // per-CTA S/R computers
    const bool book  = (rank == 0 && scomp);      // bookkeeping (seq = w)
    float Creg = 0.f;
    if (book) Creg = __ldg(g_M + n0 + w);

    // ---- t = 0: alpha0 = px[0][j] * E0; push everywhere ----
    float accv = __ldg(px + jglob) *
                 __ldcg(g_E + (size_t)(n0 + s_own) * Hn + jglob);
    {
#pragma unroll
        for (unsigned r = 0; r < K3_CL; r++) st_async_f32(a_off0, mb0, r, accv);
        float psv = accv;
#pragma unroll
        for (int o = 16; o; o >>= 1) psv += __shfl_xor_sync(0xffffffffu, psv, o);
        if (lane == 0)
#pragma unroll
            for (unsigned r = 0; r < K3_CL; r++) st_async_f32(p_off0, mb0, r, psv);
    }

    for (int t = 1; t < Tn; t++) {
        const int rp = (t - 1) & 1;               // read buffer / barrier
        const int pb = t & 1;                     // push buffer / barrier
        const unsigned mbr = rp ? mb1 : mb0;
        const unsigned mbp = pb ? mb1 : mb0;
        const unsigned parity = (unsigned)(((t - 1) >> 1) & 1);

        // prefetches (independent of exchanged data)
        float e = __ldcg(g_E + ((size_t)t * Nn + n0 + s_own) * Hn + jglob);
        float mreg = 0.f;
        if (book) mreg = __ldg(g_M + (size_t)t * Nn + n0 + w);

        mbar_wait(mbr, parity);
        if (tid == 0) mbar_expect(mbr, RX_BYTES); // re-arm for next use

        // dot: q[s][j] over this warp's 64-i chunk (broadcast LDS.128)
        unsigned long long q[K3_NP][2];
#pragma unroll
        for (int s = 0; s < K3_NP; s++) { q[s][0] = 0ull; q[s][1] = 0ull; }
#pragma unroll
        for (int s = 0; s < K3_NP; s++) {
            const ulonglong2* an = (const ulonglong2*)&buf[rp][s][w << 6];
#pragma unroll
            for (int k = 0; k < 16; k++) {
                ulonglong2 av = an[k];
                q[s][0] = ffma2(av.x, Pp[0][2 * k],     q[s][0]);
                q[s][0] = ffma2(av.y, Pp[0][2 * k + 1], q[s][0]);
                q[s][1] = ffma2(av.x, Pp[1][2 * k],     q[s][1]);
                q[s][1] = ffma2(av.y, Pp[1][2 * k + 1], q[s][1]);
            }
        }
#pragma unroll
        for (int s = 0; s < K3_NP; s++) {
#pragma unroll
            for (int j = 0; j < 2; j++) {
                float2 f = up2(q[s][j]);
                rsum[(s * 64 + lane + j * 32) * 9 + w] = f.x + f.y;
            }
        }

        // S_{t-1} + bookkeeping (off the other warps' critical path)
        if (scomp) {
            float S = 0.f;
#pragma unroll
            for (int r = 0; r < K3_CL; r++)
                S += ps[rp][r][2 * w] + ps[rp][r][2 * w + 1];
            R_s[w] = 1.0f / S;
            if (book && t < len_s[w]) Creg += __logf(S) + mreg;
        }
        __syncthreads();

        // combine + scale + push
        float tot = 0.f;
#pragma unroll
        for (int c = 0; c < 8; c++) tot += rsum[(s_own * 64 + jloc) * 9 + c];
        float newv = tot * R_s[s_own] * e;
        if (t < mylen) accv = newv;               // frozen copy-through
        const unsigned ao = pb ? a_off1 : a_off0;
#pragma unroll
        for (unsigned r = 0; r < K3_CL; r++) st_async_f32(ao, mbp, r, accv);
        float psv = accv;
#pragma unroll
        for (int o = 16; o; o >>= 1) psv += __shfl_xor_sync(0xffffffffu, psv, o);
        if (lane == 0) {
            const unsigned po = pb ? p_off1 : p_off0;
#pragma unroll
            for (unsigned r = 0; r < K3_CL; r++) st_async_f32(po, mbp, r, psv);
        }
    }

    // drain final phase (ensures all in-flight st.async delivered cluster-wide)
    mbar_wait(mb1, 1u);

    if (book) {
        float S = 0.f;
#pragma unroll
        for (int r = 0; r < K3_CL; r++)
            S += ps[1][r][2 * w] + ps[1][r][2 * w + 1];
        out[n0 + w] = Creg + logf(S);
    }
    cluster_sync_hw();                            // no early smem teardown
}

// ---------------- launch ------------------------------------------------------
extern "C" void kernel_launch(void* const* d_in, const int* in_sizes, int n_in,
                              void* d_out, int out_size) {
    const float* seq = nullptr;
    const int*   len = nullptr;
    const float* px  = nullptr;
    const float* py  = nullptr;
    for (int i = 0; i < n_in; i++) {
        switch (in_sizes[i]) {
            case Nn * Tn * Dn: seq = (const float*)d_in[i]; break;
            case Nn:           len = (const int*)d_in[i];   break;
            case Hn * Hn:      px  = (const float*)d_in[i]; break;
            case Hn * Dn:      py  = (const float*)d_in[i]; break;
        }
    }

    cudaFuncSetAttribute(hmm_k1, cudaFuncAttributeMaxDynamicSharedMemorySize, K1_SMEM);

    hmm_k0<<<64, 256>>>(py);
    hmm_k1<<<dim3(4, 512), 256, K1_SMEM>>>(seq);
    hmm_k2<<<4096, 256>>>();
    hmm_k3<<<16 * K3_CL, 256>>>(px, len, (float*)d_out);
}

// round 13
// speedup vs baseline: 1.4649x; 1.0345x over previous
#include <cuda_runtime.h>
#include <cuda_bf16.h>
#include <math.h>

// Problem dims
#define Hn 512
#define Dn 128
#define Nn 64
#define Tn 512

// K3 topology: 16 clusters x 8 CTAs. Cluster = 1 group of 4 sequences.
#define K3_CL 8
#define K3_NP 4
#define K3_JC 64
#define AP    516                 // buf row stride (floats), 16B-aligned
// per-phase incoming: 8 ranks * (128 b64 alpha msgs * 8B + 4 b32 ps * 4B)
#define RX_BYTES 8320u

// ---------------- device scratch (static globals: no allocation) -------------
__device__ float g_E[(size_t)Tn * Nn * Hn];   // emit, then exp(emit - m); [t][n][h]
__device__ float g_M[Tn * Nn];                // rowmax m[t][n]
__device__ float g_Wt[Dn * Hn];               // W^T: [d][h]
__device__ float g_bias[Hn];

// ---------------- helpers -----------------------------------------------------
__device__ __forceinline__ unsigned long long ffma2(unsigned long long a,
                                                    unsigned long long b,
                                                    unsigned long long c) {
    unsigned long long d;
    asm("fma.rn.f32x2 %0, %1, %2, %3;" : "=l"(d) : "l"(a), "l"(b), "l"(c));
    return d;
}
__device__ __forceinline__ float2 up2(unsigned long long v) {
    float2 r;
    asm("mov.b64 {%0, %1}, %2;" : "=f"(r.x), "=f"(r.y) : "l"(v));
    return r;
}
__device__ __forceinline__ unsigned long long pack2(float lo, float hi) {
    unsigned long long v;
    asm("mov.b64 %0, {%1, %2};" : "=l"(v) : "f"(lo), "f"(hi));
    return v;
}
__device__ __forceinline__ unsigned smem_u32(const void* p) {
    return (unsigned)__cvta_generic_to_shared(p);
}
__device__ __forceinline__ unsigned mapa_rank(unsigned saddr, unsigned rank) {
    unsigned r;
    asm("mapa.shared::cluster.u32 %0, %1, %2;" : "=r"(r) : "r"(saddr), "r"(rank));
    return r;
}
// Remote stores with transaction-count completion on the destination mbarrier.
__device__ __forceinline__ void st_async_f32(unsigned laddr, unsigned lmbar,
                                             unsigned rank, float v) {
    unsigned ra = mapa_rank(laddr, rank);
    unsigned rb = mapa_rank(lmbar, rank);
    asm volatile(
        "st.async.shared::cluster.mbarrier::complete_tx::bytes.b32 [%0], %1, [%2];"
        :: "r"(ra), "r"(__float_as_uint(v)), "r"(rb) : "memory");
}
__device__ __forceinline__ void st_async_b64(unsigned laddr, unsigned lmbar,
                                             unsigned rank, unsigned long long v) {
    unsigned ra = mapa_rank(laddr, rank);
    unsigned rb = mapa_rank(lmbar, rank);
    asm volatile(
        "st.async.shared::cluster.mbarrier::complete_tx::bytes.b64 [%0], %1, [%2];"
        :: "r"(ra), "l"(v), "r"(rb) : "memory");
}
__device__ __forceinline__ void mbar_init(unsigned mbar, unsigned count) {
    asm volatile("mbarrier.init.shared.b64 [%0], %1;" :: "r"(mbar), "r"(count) : "memory");
}
__device__ __forceinline__ void mbar_expect(unsigned mbar, unsigned bytes) {
    asm volatile("mbarrier.arrive.expect_tx.shared.b64 _, [%0], %1;"
                 :: "r"(mbar), "r"(bytes) : "memory");
}
__device__ __forceinline__ void mbar_wait(unsigned mbar, unsigned parity) {
    asm volatile(
        "{\n\t.reg .pred P1;\n\t"
        "WL_%=:\n\t"
        "mbarrier.try_wait.parity.acquire.cluster.shared::cta.b64 P1, [%0], %1, 0x989680;\n\t"
        "@P1 bra.uni WD_%=;\n\t"
        "bra.uni WL_%=;\n\t"
        "WD_%=:\n\t}"
        :: "r"(mbar), "r"(parity) : "memory");
}
__device__ __forceinline__ void cluster_sync_hw() {
    asm volatile("barrier.cluster.arrive.aligned;" ::: "memory");
    asm volatile("barrier.cluster.wait.aligned;" ::: "memory");
}

// ---------------- K0: W^T and bias ------------------------------------------
__global__ void hmm_k0(const float* __restrict__ py) {
    int h = blockIdx.x * 8 + (threadIdx.x >> 5);
    int lane = threadIdx.x & 31;
    float s = 0.f;
#pragma unroll
    for (int c = 0; c < 4; c++) {
        int d = lane + c * 32;
        float p = __ldg(py + (size_t)h * Dn + d);
        float l1 = log1pf(-p);
        g_Wt[(size_t)d * Hn + h] = logf(p) - l1;
        s += l1;
    }
#pragma unroll
    for (int o = 16; o; o >>= 1) s += __shfl_xor_sync(0xffffffffu, s, o);
    if (lane == 0) g_bias[h] = s;
}

// ---------------- K1: emission GEMM  emit[t][n][h] = seq[n,t,:]*W^T + b ------
#define K1_SMEM ((64 * 132 + 128 * 128) * 4)
__global__ void __launch_bounds__(256) hmm_k1(const float* __restrict__ seq) {
    extern __shared__ float sm1[];
    float* seq_s = sm1;              // [64][132]
    float* W_s   = sm1 + 64 * 132;   // [128 k][128 h]

    int tid = threadIdx.x;
    int tb = blockIdx.y;
    int h0 = blockIdx.x * 128;

    for (int idx = tid; idx < 64 * 32; idx += 256) {
        int n = idx >> 5, d4 = idx & 31;
        float4 v = __ldg((const float4*)(seq + ((size_t)n * Tn + tb) * Dn + d4 * 4));
        *(float4*)&seq_s[n * 132 + d4 * 4] = v;
    }
    for (int idx = tid; idx < 128 * 32; idx += 256) {
        int k = idx >> 5, h4 = idx & 31;
        float4 v = __ldg((const float4*)(g_Wt + (size_t)k * Hn + h0 + h4 * 4));
        *(float4*)&W_s[k * 128 + h4 * 4] = v;
    }
    __syncthreads();

    int tx = tid & 15;
    int ty = tid >> 4;
    float acc[4][8];
#pragma unroll
    for (int u = 0; u < 4; u++)
#pragma unroll
        for (int v = 0; v < 8; v++) acc[u][v] = 0.f;

#pragma unroll 4
    for (int k = 0; k < 128; k++) {
        float aa[4];
#pragma unroll
        for (int u = 0; u < 4; u++) aa[u] = seq_s[(ty * 4 + u) * 132 + k];
        float4 b0 = *(const float4*)&W_s[k * 128 + tx * 8];
        float4 b1 = *(const float4*)&W_s[k * 128 + tx * 8 + 4];
        float bb[8] = {b0.x, b0.y, b0.z, b0.w, b1.x, b1.y, b1.z, b1.w};
#pragma unroll
        for (int u = 0; u < 4; u++)
#pragma unroll
            for (int v = 0; v < 8; v++) acc[u][v] = fmaf(aa[u], bb[v], acc[u][v]);
    }

    float4 bi0 = *(const float4*)&g_bias[h0 + tx * 8];
    float4 bi1 = *(const float4*)&g_bias[h0 + tx * 8 + 4];
    float bb[8] = {bi0.x, bi0.y, bi0.z, bi0.w, bi1.x, bi1.y, bi1.z, bi1.w};
#pragma unroll
    for (int u = 0; u < 4; u++) {
        size_t r = (size_t)tb * 64 + ty * 4 + u;
        float4 o0 = make_float4(acc[u][0] + bb[0], acc[u][1] + bb[1],
                                acc[u][2] + bb[2], acc[u][3] + bb[3]);
        float4 o1 = make_float4(acc[u][4] + bb[4], acc[u][5] + bb[5],
                                acc[u][6] + bb[6], acc[u][7] + bb[7]);
        *(float4*)&g_E[r * Hn + h0 + tx * 8]     = o0;
        *(float4*)&g_E[r * Hn + h0 + tx * 8 + 4] = o1;
    }
}

// ---------------- K2: rowmax + exp(emit - m), in place; write m --------------
__global__ void __launch_bounds__(256) hmm_k2() {
    int r = blockIdx.x * 8 + (threadIdx.x >> 5);
    int lane = threadIdx.x & 31;
    float* row = g_E + (size_t)r * Hn;
    float4 v[4];
    float m = -3.0e38f;
#pragma unroll
    for (int c = 0; c < 4; c++) {
        v[c] = *(const float4*)(row + c * 128 + lane * 4);
        m = fmaxf(m, fmaxf(fmaxf(v[c].x, v[c].y), fmaxf(v[c].z, v[c].w)));
    }
#pragma unroll
    for (int o = 16; o; o >>= 1) m = fmaxf(m, __shfl_xor_sync(0xffffffffu, m, o));
#pragma unroll
    for (int c = 0; c < 4; c++) {
        float4 e = make_float4(__expf(v[c].x - m), __expf(v[c].y - m),
                               __expf(v[c].z - m), __expf(v[c].w - m));
        *(float4*)(row + c * 128 + lane * 4) = e;
    }
    if (lane == 0) g_M[r] = m;
}

// ---------------- K3: cluster st.async scaled-forward (b64 exchange) ---------
// Roles:
//   dot:     all 8 warps; warp w: i-chunk [64w,64w+64), j-cols {lane, lane+32}
//   combine: tid < 128: warp w(<4) = sequence, lane pr: j-pair {2pr, 2pr+1}
__global__ void __launch_bounds__(256, 1) __cluster_dims__(K3_CL, 1, 1)
hmm_k3(const float* __restrict__ px, const int* __restrict__ lengths,
       float* __restrict__ out) {
    __shared__ float buf[2][K3_NP][AP];     // incoming alpha, double-buffered
    __shared__ float rsum[256 * 9];         // partials [(s*64+jloc)*9 + chunk]
    __shared__ float ps[2][K3_CL][K3_NP];   // per-rank per-seq partial sums
    __shared__ float R_s[K3_NP];            // 1/S per sequence
    __shared__ int   len_s[K3_NP];
    __shared__ unsigned long long mbar[2];

    const int tid  = threadIdx.x;
    const int w    = tid >> 5;
    const int lane = tid & 31;
    unsigned rank;
    asm("mov.u32 %0, %%cluster_ctarank;" : "=r"(rank));
    const int grp = blockIdx.x >> 3;             // cluster id 0..15
    const int n0  = grp * K3_NP;

    // combine-owner identity (tid < 128): seq = w, j-pair = 2*lane
    const bool owner = (w < K3_NP);
    const int  jloc  = 2 * lane;                 // even local column
    const int  jglob = (int)rank * K3_JC + jloc;
    // dot identity j-columns
    const int jg0 = (int)rank * K3_JC + lane;
    const int jg1 = jg0 + 32;

    const unsigned mb0 = smem_u32(&mbar[0]);
    const unsigned mb1 = smem_u32(&mbar[1]);

    // P slice -> registers: Pp[j][k] packs P[64w+2k][jg_j], P[64w+2k+1][jg_j]
    unsigned long long Pp[2][32];
#pragma unroll
    for (int k = 0; k < 32; k++) {
        const float* pr0 = px + (size_t)(w * 64 + 2 * k) * Hn;
        const float* pr1 = px + (size_t)(w * 64 + 2 * k + 1) * Hn;
        Pp[0][k] = pack2(__ldg(pr0 + jg0), __ldg(pr1 + jg0));
        Pp[1][k] = pack2(__ldg(pr0 + jg1), __ldg(pr1 + jg1));
    }
    if (tid == 0) {
        mbar_init(mb0, 1);
        mbar_init(mb1, 1);
    }
    if (tid < K3_NP) len_s[tid] = __ldg(lengths + n0 + tid);
    __syncthreads();
    if (tid == 0) {                               // arm both phases' tx counts
        mbar_expect(mb0, RX_BYTES);
        mbar_expect(mb1, RX_BYTES);
    }
    const int mylen = owner ? len_s[w] : 0;
    cluster_sync_hw();                            // one-time: inits visible

    // push addresses (local-equivalent offsets, same in every rank)
    const unsigned a_off0 = owner ? smem_u32(&buf[0][w][jglob]) : 0u;
    const unsigned a_off1 = owner ? smem_u32(&buf[1][w][jglob]) : 0u;
    const unsigned p_off0 = smem_u32(&ps[0][rank][w & 3]);
    const unsigned p_off1 = smem_u32(&ps[1][rank][w & 3]);

    const bool scomp = (owner && lane == 0);      // per-CTA S/R computers
    const bool book  = (rank == 0 && scomp);      // bookkeeping (seq = w)
    float Creg = 0.f;
    if (book) Creg = __ldg(g_M + n0 + w);

    // ---- t = 0: alpha0 = px[0][j] * E0; push everywhere ----
    float2 accv = make_float2(0.f, 0.f);
    if (owner) {
        float2 e0 = __ldcg((const float2*)(g_E + (size_t)(n0 + w) * Hn + jglob));
        accv.x = __ldg(px + jglob) * e0.x;
        accv.y = __ldg(px + jglob + 1) * e0.y;
#pragma unroll
        for (unsigned i = 0; i < K3_CL; i++) {
            unsigned r = (rank + i) & 7u;
            st_async_b64(a_off0, mb0, r, pack2(accv.x, accv.y));
        }
        float psv = accv.x + accv.y;
#pragma unroll
        for (int o = 16; o; o >>= 1) psv += __shfl_xor_sync(0xffffffffu, psv, o);
        if (lane == 0)
#pragma unroll
            for (unsigned i = 0; i < K3_CL; i++) {
                unsigned r = (rank + i) & 7u;
                st_async_f32(p_off0, mb0, r, psv);
            }
    }

    for (int t = 1; t < Tn; t++) {
        const int rp = (t - 1) & 1;               // read buffer / barrier
        const int pb = t & 1;                     // push buffer / barrier
        const unsigned mbr = rp ? mb1 : mb0;
        const unsigned mbp = pb ? mb1 : mb0;
        const unsigned parity = (unsigned)(((t - 1) >> 1) & 1);

        // prefetches (independent of exchanged data)
        float2 e = make_float2(0.f, 0.f);
        float mreg = 0.f;
        if (owner) {
            e = __ldcg((const float2*)(g_E + ((size_t)t * Nn + n0 + w) * Hn + jglob));
            if (lane == 0 && rank == 0)
                mreg = __ldg(g_M + (size_t)t * Nn + n0 + w);
        }

        mbar_wait(mbr, parity);
        if (tid == 0) mbar_expect(mbr, RX_BYTES); // re-arm for next use

        // dot: q[s][j] over this warp's 64-i chunk (broadcast LDS.128)
        unsigned long long q[K3_NP][2];
#pragma unroll
        for (int s = 0; s < K3_NP; s++) { q[s][0] = 0ull; q[s][1] = 0ull; }
#pragma unroll
        for (int s = 0; s < K3_NP; s++) {
            const ulonglong2* an = (const ulonglong2*)&buf[rp][s][w << 6];
#pragma unroll
            for (int k = 0; k < 16; k++) {
                ulonglong2 av = an[k];
                q[s][0] = ffma2(av.x, Pp[0][2 * k],     q[s][0]);
                q[s][0] = ffma2(av.y, Pp[0][2 * k + 1], q[s][0]);
                q[s][1] = ffma2(av.x, Pp[1][2 * k],     q[s][1]);
                q[s][1] = ffma2(av.y, Pp[1][2 * k + 1], q[s][1]);
            }
        }
#pragma unroll
        for (int s = 0; s < K3_NP; s++) {
#pragma unroll
            for (int j = 0; j < 2; j++) {
                float2 f = up2(q[s][j]);
                rsum[(s * 64 + lane + j * 32) * 9 + w] = f.x + f.y;
            }
        }

        // S_{t-1} + bookkeeping (parallel with other warps' rsum stores)
        if (scomp) {
            float S = 0.f;
#pragma unroll
            for (int r = 0; r < K3_CL; r++) S += ps[rp][r][w];
            R_s[w] = 1.0f / S;
            if (book && t < len_s[w]) Creg += __logf(S) + mreg;
        }
        __syncthreads();

        // combine 8 chunks for j-pair, scale, push as one b64 per rank
        if (owner) {
            float t0 = 0.f, t1 = 0.f;
            const float* r0 = rsum + (w * 64 + jloc) * 9;
#pragma unroll
            for (int c = 0; c < 8; c++) { t0 += r0[c]; t1 += r0[9 + c]; }
            float Rv = R_s[w];
            float n0v = t0 * Rv * e.x;
            float n1v = t1 * Rv * e.y;
            if (t < mylen) { accv.x = n0v; accv.y = n1v; }   // frozen copy-through
            const unsigned ao = pb ? a_off1 : a_off0;
            unsigned long long pk = pack2(accv.x, accv.y);
#pragma unroll
            for (unsigned i = 0; i < K3_CL; i++) {
                unsigned r = (rank + i) & 7u;
                st_async_b64(ao, mbp, r, pk);
            }
            float psv = accv.x + accv.y;
#pragma unroll
            for (int o = 16; o; o >>= 1) psv += __shfl_xor_sync(0xffffffffu, psv, o);
            if (lane == 0) {
                const unsigned po = pb ? p_off1 : p_off0;
#pragma unroll
                for (unsigned i = 0; i < K3_CL; i++) {
                    unsigned r = (rank + i) & 7u;
                    st_async_f32(po, mbp, r, psv);
                }
            }
        }
    }

    // drain final phase (ensures all in-flight st.async delivered cluster-wide)
    mbar_wait(mb1, 1u);

    if (book) {
        float S = 0.f;
#pragma unroll
        for (int r = 0; r < K3_CL; r++) S += ps[1][r][w];
        out[n0 + w] = Creg + logf(S);
    }
    cluster_sync_hw();                            // no early smem teardown
}

// ---------------- launch ------------------------------------------------------
extern "C" void kernel_launch(void* const* d_in, const int* in_sizes, int n_in,
                              void* d_out, int out_size) {
    const float* seq = nullptr;
    const int*   len = nullptr;
    const float* px  = nullptr;
    const float* py  = nullptr;
    for (int i = 0; i < n_in; i++) {
        switch (in_sizes[i]) {
            case Nn * Tn * Dn: seq = (const float*)d_in[i]; break;
            case Nn:           len = (const int*)d_in[i];   break;
            case Hn * Hn:      px  = (const float*)d_in[i]; break;
            case Hn * Dn:      py  = (const float*)d_in[i]; break;
        }
    }

    cudaFuncSetAttribute(hmm_k1, cudaFuncAttributeMaxDynamicSharedMemorySize, K1_SMEM);

    hmm_k0<<<64, 256>>>(py);
    hmm_k1<<<dim3(4, 512), 256, K1_SMEM>>>(seq);
    hmm_k2<<<4096, 256>>>();
    hmm_k3<<<16 * K3_CL, 256>>>(px, len, (float*)d_out);
}